// round 3
// baseline (speedup 1.0000x reference)
#include <cuda_runtime.h>
#include <cstdint>

#define NODES 50000
#define EDGES 800000
// dims: IN=128, HID=256, LAT=64

// ---------------- scratch (static device arrays; no allocation) ----------------
__device__ int   g_is64;
__device__ int   g_cnt[NODES];
__device__ int   g_off[NODES + 1];
__device__ int   g_cur[NODES];
__device__ int   g_srcs[EDGES];
__device__ float g_meanx[(size_t)NODES * 128];
__device__ float g_h[(size_t)NODES * 256];
__device__ float g_q[(size_t)NODES * 64];
__device__ float g_r[(size_t)NODES * 64];

// ---------------- edge dtype detection (int64 vs int32) ----------------
// All indices are < 50000 < 2^31. If data is int64, every odd int32 word
// (the high half) is 0. If int32, odd words are random indices (P(all 8
// zero) ~ (1/50000)^8 ~ 0).
__global__ void k_detect(const int* __restrict__ ei32) {
    if (threadIdx.x == 0 && blockIdx.x == 0) {
        int is64 = 1;
        #pragma unroll
        for (int k = 1; k < 16; k += 2)
            if (ei32[k] != 0) is64 = 0;
        g_is64 = is64;
    }
}

__device__ __forceinline__ int load_idx(const void* ei, int pos) {
    if (g_is64) return (int)((const long long*)ei)[pos];
    return ((const int*)ei)[pos];
}

// ---------------- CSR build ----------------
__global__ void k_zero() {
    int i = blockIdx.x * blockDim.x + threadIdx.x;
    if (i < NODES) g_cnt[i] = 0;
}

__global__ void k_count(const void* __restrict__ ei) {
    int e = blockIdx.x * blockDim.x + threadIdx.x;
    if (e < EDGES) atomicAdd(&g_cnt[load_idx(ei, EDGES + e)], 1);
}

// single-block chunked exclusive scan of g_cnt -> g_off, g_cur
__global__ void k_scan() {
    __shared__ int warp_sums[32];
    __shared__ int s_carry;
    const int tid = threadIdx.x;
    const int lane = tid & 31;
    const int wid = tid >> 5;
    if (tid == 0) s_carry = 0;
    __syncthreads();
    for (int base = 0; base < NODES; base += 1024) {
        int i = base + tid;
        int v = (i < NODES) ? g_cnt[i] : 0;
        int s = v;
        #pragma unroll
        for (int d = 1; d < 32; d <<= 1) {
            int t = __shfl_up_sync(0xFFFFFFFFu, s, d);
            if (lane >= d) s += t;
        }
        if (lane == 31) warp_sums[wid] = s;
        __syncthreads();
        if (wid == 0) {
            int ws = warp_sums[lane];
            int t2 = ws;
            #pragma unroll
            for (int d = 1; d < 32; d <<= 1) {
                int t = __shfl_up_sync(0xFFFFFFFFu, t2, d);
                if (lane >= d) t2 += t;
            }
            warp_sums[lane] = t2 - ws;  // exclusive warp offsets
        }
        __syncthreads();
        int excl = (s - v) + warp_sums[wid] + s_carry;
        if (i < NODES) { g_off[i] = excl; g_cur[i] = excl; }
        __syncthreads();
        if (tid == 1023) s_carry = excl + v;
        __syncthreads();
    }
    if (tid == 0) g_off[NODES] = s_carry;
}

__global__ void k_scatter(const void* __restrict__ ei) {
    int e = blockIdx.x * blockDim.x + threadIdx.x;
    if (e < EDGES) {
        int d = load_idx(ei, EDGES + e);
        int s = load_idx(ei, e);
        int p = atomicAdd(&g_cur[d], 1);
        g_srcs[p] = s;
    }
}

// ---------------- layer-1 aggregation: g_meanx[i] = mean_{j in N(i)} x[j] ----------------
// one warp per node; each lane owns 4 of the 128 features (float4)
__global__ void __launch_bounds__(256) k_agg1(const float* __restrict__ x) {
    const int node = blockIdx.x * 8 + (threadIdx.x >> 5);
    const int lane = threadIdx.x & 31;
    if (node >= NODES) return;
    const int s0 = g_off[node], s1 = g_off[node + 1];
    float4 acc = make_float4(0.f, 0.f, 0.f, 0.f);
    int j = s0;
    for (; j + 1 < s1; j += 2) {
        int sa = g_srcs[j];
        int sb = g_srcs[j + 1];
        float4 va = ((const float4*)(x + (size_t)sa * 128))[lane];
        float4 vb = ((const float4*)(x + (size_t)sb * 128))[lane];
        acc.x += va.x; acc.y += va.y; acc.z += va.z; acc.w += va.w;
        acc.x += vb.x; acc.y += vb.y; acc.z += vb.z; acc.w += vb.w;
    }
    if (j < s1) {
        int sa = g_srcs[j];
        float4 va = ((const float4*)(x + (size_t)sa * 128))[lane];
        acc.x += va.x; acc.y += va.y; acc.z += va.z; acc.w += va.w;
    }
    int deg = s1 - s0;
    float inv = 1.0f / (float)(deg > 0 ? deg : 1);
    acc.x *= inv; acc.y *= inv; acc.z *= inv; acc.w *= inv;
    ((float4*)(g_meanx + (size_t)node * 128))[lane] = acc;
}

// ---------------- layer-1 GEMM: h = relu(meanx @ W1l + x @ W1r + b1) ----------------
// tile 128x128, 256 threads, 8x8 microtile, K=128 (two passes: meanx/W1l, x/W1r)
__global__ void __launch_bounds__(256) k_gemm1(const float* __restrict__ x,
                                               const float* __restrict__ W1l,
                                               const float* __restrict__ W1r,
                                               const float* __restrict__ b1) {
    __shared__ float As[16][132];
    __shared__ float Bs[16][128];
    const int col0 = blockIdx.x * 128;   // 0 or 128 of 256 output cols
    const int row0 = blockIdx.y * 128;
    const int tid = threadIdx.x;
    const int tx = tid & 15;             // cols tx*8..tx*8+7
    const int ty = tid >> 4;             // rows ty*8..ty*8+7
    const int lm = tid >> 1;             // A-tile load: row within tile
    const int lk = (tid & 1) * 8;        // A-tile load: k offset
    const int bk = tid >> 4;             // B-tile load: k row
    const int bc = (tid & 15) * 8;       // B-tile load: col offset

    float acc[8][8];
    #pragma unroll
    for (int i = 0; i < 8; i++)
        #pragma unroll
        for (int jj = 0; jj < 8; jj++) acc[i][jj] = 0.f;

    #pragma unroll 1
    for (int pass = 0; pass < 2; pass++) {
        const float* A = pass ? x : g_meanx;       // [N,128]
        const float* W = pass ? W1r : W1l;         // [128,256]
        #pragma unroll 1
        for (int k0 = 0; k0 < 128; k0 += 16) {
            int r = row0 + lm;
            float4 a0 = make_float4(0.f,0.f,0.f,0.f), a1 = make_float4(0.f,0.f,0.f,0.f);
            if (r < NODES) {
                const float4* p = (const float4*)(A + (size_t)r * 128 + k0 + lk);
                a0 = p[0]; a1 = p[1];
            }
            As[lk + 0][lm] = a0.x; As[lk + 1][lm] = a0.y;
            As[lk + 2][lm] = a0.z; As[lk + 3][lm] = a0.w;
            As[lk + 4][lm] = a1.x; As[lk + 5][lm] = a1.y;
            As[lk + 6][lm] = a1.z; As[lk + 7][lm] = a1.w;
            const float4* q = (const float4*)(W + (size_t)(k0 + bk) * 256 + col0 + bc);
            *(float4*)&Bs[bk][bc] = q[0];
            *(float4*)&Bs[bk][bc + 4] = q[1];
            __syncthreads();
            #pragma unroll
            for (int k = 0; k < 16; k++) {
                float4 a0v = *(const float4*)&As[k][ty * 8];
                float4 a1v = *(const float4*)&As[k][ty * 8 + 4];
                float4 b0v = *(const float4*)&Bs[k][tx * 8];
                float4 b1v = *(const float4*)&Bs[k][tx * 8 + 4];
                float a[8] = {a0v.x, a0v.y, a0v.z, a0v.w, a1v.x, a1v.y, a1v.z, a1v.w};
                float b[8] = {b0v.x, b0v.y, b0v.z, b0v.w, b1v.x, b1v.y, b1v.z, b1v.w};
                #pragma unroll
                for (int i = 0; i < 8; i++)
                    #pragma unroll
                    for (int jj = 0; jj < 8; jj++)
                        acc[i][jj] = fmaf(a[i], b[jj], acc[i][jj]);
            }
            __syncthreads();
        }
    }
    // epilogue: + b1, relu, store h
    #pragma unroll
    for (int i = 0; i < 8; i++) {
        int r = row0 + ty * 8 + i;
        if (r < NODES) {
            #pragma unroll
            for (int jj = 0; jj < 8; jj += 4) {
                int c = col0 + tx * 8 + jj;
                float4 bb = *(const float4*)&b1[c];
                float4 o;
                o.x = fmaxf(acc[i][jj + 0] + bb.x, 0.f);
                o.y = fmaxf(acc[i][jj + 1] + bb.y, 0.f);
                o.z = fmaxf(acc[i][jj + 2] + bb.z, 0.f);
                o.w = fmaxf(acc[i][jj + 3] + bb.w, 0.f);
                *(float4*)&g_h[(size_t)r * 256 + c] = o;
            }
        }
    }
}

// ---------------- layer-2 GEMMs: q = h @ W2l ; r = h @ W2r + b2 ----------------
// tile 128x64, 256 threads, 8x4 microtile, K=256. blockIdx.x picks output.
__global__ void __launch_bounds__(256) k_gemm2(const float* __restrict__ W2l,
                                               const float* __restrict__ W2r,
                                               const float* __restrict__ b2) {
    __shared__ float As[16][132];
    __shared__ float Bs[16][64];
    const float* B;
    float* out;
    bool has_bias;
    if (blockIdx.x == 0) { B = W2l; out = g_q; has_bias = false; }
    else                 { B = W2r; out = g_r; has_bias = true;  }
    const int row0 = blockIdx.y * 128;
    const int tid = threadIdx.x;
    const int tx = tid & 15;            // cols tx*4..tx*4+3
    const int ty = tid >> 4;            // rows ty*8..ty*8+7
    const int lm = tid >> 1;
    const int lk = (tid & 1) * 8;
    const int bk = tid >> 4;
    const int bc = (tid & 15) * 4;

    float acc[8][4];
    #pragma unroll
    for (int i = 0; i < 8; i++)
        #pragma unroll
        for (int jj = 0; jj < 4; jj++) acc[i][jj] = 0.f;

    #pragma unroll 1
    for (int k0 = 0; k0 < 256; k0 += 16) {
        int r = row0 + lm;
        float4 a0 = make_float4(0.f,0.f,0.f,0.f), a1 = make_float4(0.f,0.f,0.f,0.f);
        if (r < NODES) {
            const float4* p = (const float4*)(g_h + (size_t)r * 256 + k0 + lk);
            a0 = p[0]; a1 = p[1];
        }
        As[lk + 0][lm] = a0.x; As[lk + 1][lm] = a0.y;
        As[lk + 2][lm] = a0.z; As[lk + 3][lm] = a0.w;
        As[lk + 4][lm] = a1.x; As[lk + 5][lm] = a1.y;
        As[lk + 6][lm] = a1.z; As[lk + 7][lm] = a1.w;
        *(float4*)&Bs[bk][bc] = *(const float4*)(B + (size_t)(k0 + bk) * 64 + bc);
        __syncthreads();
        #pragma unroll
        for (int k = 0; k < 16; k++) {
            float4 a0v = *(const float4*)&As[k][ty * 8];
            float4 a1v = *(const float4*)&As[k][ty * 8 + 4];
            float4 bv  = *(const float4*)&Bs[k][tx * 4];
            float a[8] = {a0v.x, a0v.y, a0v.z, a0v.w, a1v.x, a1v.y, a1v.z, a1v.w};
            float b[4] = {bv.x, bv.y, bv.z, bv.w};
            #pragma unroll
            for (int i = 0; i < 8; i++)
                #pragma unroll
                for (int jj = 0; jj < 4; jj++)
                    acc[i][jj] = fmaf(a[i], b[jj], acc[i][jj]);
        }
        __syncthreads();
    }
    float4 bb = make_float4(0.f,0.f,0.f,0.f);
    if (has_bias) bb = *(const float4*)&b2[tx * 4];
    #pragma unroll
    for (int i = 0; i < 8; i++) {
        int r = row0 + ty * 8 + i;
        if (r < NODES) {
            float4 o;
            o.x = acc[i][0] + bb.x;
            o.y = acc[i][1] + bb.y;
            o.z = acc[i][2] + bb.z;
            o.w = acc[i][3] + bb.w;
            *(float4*)&out[(size_t)r * 64 + tx * 4] = o;
        }
    }
}

// ---------------- layer-2 aggregation + z + fused decoder ----------------
// z[i] = mean_{j in N(i)} q[j] + r[i] ;  x_hat[i] = z[i] @ Wd + bd
// one warp per node; Wd (64x128 = 32KB) staged in smem per block.
__global__ void __launch_bounds__(256) k_agg2(const float* __restrict__ Wd,
                                              const float* __restrict__ bd,
                                              float* __restrict__ z_out,
                                              float* __restrict__ xh_out) {
    __shared__ float4 sWd[64 * 32];   // [k][c4]: Wd row-major as float4
    __shared__ float  sZ[8][64];
    for (int i = threadIdx.x; i < 64 * 32; i += blockDim.x)
        sWd[i] = ((const float4*)Wd)[i];
    __syncthreads();

    const int wid = threadIdx.x >> 5;
    const int lane = threadIdx.x & 31;
    const int node = blockIdx.x * 8 + wid;
    if (node < NODES) {
        const int s0 = g_off[node], s1 = g_off[node + 1];
        float2 acc = make_float2(0.f, 0.f);
        int j = s0;
        for (; j + 1 < s1; j += 2) {
            int sa = g_srcs[j];
            int sb = g_srcs[j + 1];
            float2 va = ((const float2*)(g_q + (size_t)sa * 64))[lane];
            float2 vb = ((const float2*)(g_q + (size_t)sb * 64))[lane];
            acc.x += va.x + vb.x;
            acc.y += va.y + vb.y;
        }
        if (j < s1) {
            int sa = g_srcs[j];
            float2 va = ((const float2*)(g_q + (size_t)sa * 64))[lane];
            acc.x += va.x; acc.y += va.y;
        }
        int deg = s1 - s0;
        float inv = 1.0f / (float)(deg > 0 ? deg : 1);
        float2 r2 = ((const float2*)(g_r + (size_t)node * 64))[lane];
        float2 zv;
        zv.x = acc.x * inv + r2.x;
        zv.y = acc.y * inv + r2.y;
        ((float2*)(z_out + (size_t)node * 64))[lane] = zv;
        sZ[wid][lane * 2]     = zv.x;
        sZ[wid][lane * 2 + 1] = zv.y;
        __syncwarp();
        // decoder: each lane computes output cols [lane*4, lane*4+4)
        float4 o = ((const float4*)bd)[lane];
        #pragma unroll 8
        for (int k = 0; k < 64; k++) {
            float zk = sZ[wid][k];
            float4 w = sWd[k * 32 + lane];
            o.x = fmaf(zk, w.x, o.x);
            o.y = fmaf(zk, w.y, o.y);
            o.z = fmaf(zk, w.z, o.z);
            o.w = fmaf(zk, w.w, o.w);
        }
        ((float4*)(xh_out + (size_t)node * 128))[lane] = o;
    }
}

// ---------------- launcher ----------------
extern "C" void kernel_launch(void* const* d_in, const int* in_sizes, int n_in,
                              void* d_out, int out_size) {
    const float* x   = (const float*)d_in[0];
    const void*  ei  = d_in[1];
    const float* W1l = (const float*)d_in[2];
    const float* b1  = (const float*)d_in[3];
    const float* W1r = (const float*)d_in[4];
    const float* W2l = (const float*)d_in[5];
    const float* b2  = (const float*)d_in[6];
    const float* W2r = (const float*)d_in[7];
    const float* Wd  = (const float*)d_in[8];
    const float* bd  = (const float*)d_in[9];

    float* z_out  = (float*)d_out;                       // [N,64]
    float* xh_out = (float*)d_out + (size_t)NODES * 64;  // [N,128]

    k_detect<<<1, 32>>>((const int*)ei);
    k_zero<<<(NODES + 255) / 256, 256>>>();
    k_count<<<(EDGES + 255) / 256, 256>>>(ei);
    k_scan<<<1, 1024>>>();
    k_scatter<<<(EDGES + 255) / 256, 256>>>(ei);
    k_agg1<<<(NODES + 7) / 8, 256>>>(x);
    k_gemm1<<<dim3(2, (NODES + 127) / 128), 256>>>(x, W1l, W1r, b1);
    k_gemm2<<<dim3(2, (NODES + 127) / 128), 256>>>(W2l, W2r, b2);
    k_agg2<<<(NODES + 7) / 8, 256>>>(Wd, bd, z_out, xh_out);
}